// round 5
// baseline (speedup 1.0000x reference)
#include <cuda_runtime.h>
#include <cuda_bf16.h>
#include <math.h>
#include <stdint.h>

#define BB      32
#define TSLEN   256
#define DD      256
#define FF      256
#define MAXMEL  2048
#define NBINS   256

#define OUT_ELEMS   (BB*MAXMEL*2*DD)
#define LOGDUR_OFF  OUT_ELEMS
#define PITCH_OFF   (LOGDUR_OFF + BB*TSLEN)
#define MEL_OFF     (PITCH_OFF + BB*MAXMEL)

#define WCONV (256*768)
#define WPROJ (512*256)

typedef __nv_bfloat16 bf16;

// ---------------- scratch (static device globals; no allocation) -------------
__device__ float g_bufX[BB*MAXMEL*DD];          // gathered fp32 (for emb add)
__device__ float g_bufB[BB*MAXMEL*FF];          // conv2 output (fp32, heads read it)
__device__ bf16  g_xh[BB*MAXMEL*DD];            // activation hi (pitch/proj input)
__device__ bf16  g_xl[BB*MAXMEL*DD];            // activation lo
__device__ bf16  g_yh[BB*MAXMEL*FF];            // conv1 output hi
__device__ bf16  g_yl[BB*MAXMEL*FF];            // conv1 output lo
__device__ bf16  g_dh[BB*TSLEN*DD];             // dur-path ling hi
__device__ bf16  g_dl[BB*TSLEN*DD];             // dur-path ling lo
__device__ bf16  g_wh[4*WCONV + WPROJ];
__device__ bf16  g_wl[4*WCONV + WPROJ];
__device__ int   g_idx[BB*MAXMEL];
__device__ int   g_mellen[BB];

// ---------------- helpers -----------------------------------------------------
__device__ __forceinline__ void cpa16(uint32_t d, const void* s, int sz) {
    asm volatile("cp.async.ca.shared.global [%0], [%1], 16, %2;" :: "r"(d), "l"(s), "r"(sz));
}
__device__ __forceinline__ void ldm4(uint32_t* r, uint32_t a) {
    asm volatile("ldmatrix.sync.aligned.m8n8.x4.shared.b16 {%0,%1,%2,%3}, [%4];"
        : "=r"(r[0]), "=r"(r[1]), "=r"(r[2]), "=r"(r[3]) : "r"(a));
}
__device__ __forceinline__ void mma16816(float* c, const uint32_t* a, uint32_t b0, uint32_t b1) {
    asm volatile(
        "mma.sync.aligned.m16n8k16.row.col.f32.bf16.bf16.f32 "
        "{%0,%1,%2,%3}, {%4,%5,%6,%7}, {%8,%9}, {%0,%1,%2,%3};"
        : "+f"(c[0]), "+f"(c[1]), "+f"(c[2]), "+f"(c[3])
        : "r"(a[0]), "r"(a[1]), "r"(a[2]), "r"(a[3]), "r"(b0), "r"(b1));
}
__device__ __forceinline__ void split1(float x, bf16& h, bf16& l) {
    h = __float2bfloat16_rn(x);
    l = __float2bfloat16_rn(x - __bfloat162float(h));
}
__device__ __forceinline__ uint32_t packbf(float a, float b) {
    bf16 x = __float2bfloat16_rn(a), y = __float2bfloat16_rn(b);
    return (uint32_t)__bfloat16_as_ushort(x) | ((uint32_t)__bfloat16_as_ushort(y) << 16);
}

// SMEM: A tiles 128x40 halfwords (10240 B), B tiles 256x40 halfwords (20480 B)
#define SOFF_AHI(b) ((b)*10240)
#define SOFF_ALO(b) (20480 + (b)*10240)
#define SOFF_BHI(b) (40960 + (b)*20480)
#define SOFF_BLO(b) (81920 + (b)*20480)
#define SM_TOTAL 122880

// ---------------- weight prep: fp32 -> bf16 hi/lo, transposed ---------------
__global__ void prep_w_conv_bf(const float* __restrict__ W,
                               bf16* __restrict__ H, bf16* __restrict__ L) {
    int o = blockIdx.x * 256 + threadIdx.x;      // < 196608
    int f = o / 768;
    int r = o - f * 768;
    int tap = r >> 8;
    int c = r & 255;
    float w = W[f*768 + c*3 + tap];
    bf16 h, l; split1(w, h, l);
    H[o] = h; L[o] = l;
}
__global__ void prep_w_proj_bf(const float* __restrict__ W,
                               bf16* __restrict__ H, bf16* __restrict__ L) {
    int o = blockIdx.x * 256 + threadIdx.x;      // < 131072
    int n = o >> 8;
    int k = o & 255;
    float w = W[k*512 + n];
    bf16 h, l; split1(w, h, l);
    H[o] = h; L[o] = l;
}

// ---------------- split fp32 activations -> bf16 hi/lo -----------------------
__global__ void split_f32(const float* __restrict__ in, bf16* __restrict__ hi,
                          bf16* __restrict__ lo) {
    int i = blockIdx.x * 256 + threadIdx.x;
    float4 v = ((const float4*)in)[i];
    bf16 h0,h1,h2,h3, l0,l1,l2,l3;
    split1(v.x,h0,l0); split1(v.y,h1,l1); split1(v.z,h2,l2); split1(v.w,h3,l3);
    ((ushort4*)hi)[i] = make_ushort4(__bfloat16_as_ushort(h0), __bfloat16_as_ushort(h1),
                                     __bfloat16_as_ushort(h2), __bfloat16_as_ushort(h3));
    ((ushort4*)lo)[i] = make_ushort4(__bfloat16_as_ushort(l0), __bfloat16_as_ushort(l1),
                                     __bfloat16_as_ushort(l2), __bfloat16_as_ushort(l3));
}

// ---------------- length regulator -------------------------------------------
__global__ void length_reg(const int* __restrict__ dur, int* __restrict__ idxb,
                           int* __restrict__ mellen, float* __restrict__ out_mel) {
    __shared__ int cum[TSLEN];
    int b = blockIdx.x;
    int t = threadIdx.x;
    cum[t] = dur[b*TSLEN + t];
    __syncthreads();
    for (int off = 1; off < TSLEN; off <<= 1) {
        int v = (t >= off) ? cum[t - off] : 0;
        __syncthreads();
        cum[t] += v;
        __syncthreads();
    }
    int ml = min(cum[TSLEN-1], MAXMEL);
    if (t == 0) { mellen[b] = ml; out_mel[b] = (float)ml; }
    for (int m = t; m < MAXMEL; m += TSLEN) {
        int lo = 0, hi = TSLEN;
        while (lo < hi) { int mid = (lo + hi) >> 1; if (cum[mid] <= m) lo = mid + 1; else hi = mid; }
        idxb[b*MAXMEL + m] = min(lo, TSLEN - 1);
    }
}

// ---------------- gather expanded x + fused hi/lo split ----------------------
__global__ void gather_x(const float* __restrict__ ling, const int* __restrict__ idxb,
                         const int* __restrict__ mellen) {
    int row = blockIdx.x;
    int b = row >> 11;
    int m = row & (MAXMEL - 1);
    bool masked = (m >= mellen[b]);
    int src = idxb[row];
    const float4* s = (const float4*)(ling + ((size_t)b*TSLEN + src)*DD);
    float4 v = masked ? make_float4(0.f,0.f,0.f,0.f) : s[threadIdx.x];
    ((float4*)(g_bufX + (size_t)row*DD))[threadIdx.x] = v;
    bf16 h0,h1,h2,h3, l0,l1,l2,l3;
    split1(v.x,h0,l0); split1(v.y,h1,l1); split1(v.z,h2,l2); split1(v.w,h3,l3);
    ((ushort4*)(g_xh + (size_t)row*DD))[threadIdx.x] =
        make_ushort4(__bfloat16_as_ushort(h0), __bfloat16_as_ushort(h1),
                     __bfloat16_as_ushort(h2), __bfloat16_as_ushort(h3));
    ((ushort4*)(g_xl + (size_t)row*DD))[threadIdx.x] =
        make_ushort4(__bfloat16_as_ushort(l0), __bfloat16_as_ushort(l1),
                     __bfloat16_as_ushort(l2), __bfloat16_as_ushort(l3));
}

// ---------------- fused HMMA GEMM: 128x256 CTA tile, fused LN/split ----------
// A: bf16 hi/lo [rows][256]; W: bf16 hi/lo [Cout][K]; 3-term hi/lo MMA.
// LNORM: relu + per-row LayerNorm in epilogue. OUTBF: write bf16 hi/lo.
template<int KWIN, bool LNORM, bool MASK, bool OUTBF, int TSHIFT>
__global__ __launch_bounds__(256, 1)
void gemm_big(const bf16* __restrict__ Ahi, const bf16* __restrict__ Alo,
              const bf16* __restrict__ Whi, const bf16* __restrict__ Wlo,
              const float* __restrict__ bias,
              const float* __restrict__ gam, const float* __restrict__ bet,
              float* __restrict__ Yf, bf16* __restrict__ Yh, bf16* __restrict__ Yl,
              int Cout, const int* __restrict__ mellen) {
    constexpr int Tb = 1 << TSHIFT;
    constexpr int NS = KWIN * 8;
    constexpr int K  = KWIN * 256;
    extern __shared__ char smc[];
    const uint32_t sb = (uint32_t)__cvta_generic_to_shared(smc);

    const int tid = threadIdx.x;
    const int wid = tid >> 5, lid = tid & 31;
    const int wm = wid >> 1, wn = wid & 1;          // 4 x 2 warps; warp tile 32x128
    const int row0 = blockIdx.x * 128;
    const int n0   = blockIdx.y * 256;
    const int tloc0 = row0 & (Tb - 1);
    const int gseg  = row0 - tloc0;
    const int bIdx  = row0 >> TSHIFT;

    const uint32_t aoff = (uint32_t)(wm*2560 + ((lid & 15)*40 + ((lid & 16) ? 8 : 0))*2);
    const uint32_t boff = (uint32_t)(wn*10240 + (((lid & 7) + ((lid & 16) ? 8 : 0))*40
                                               + ((lid & 8) ? 8 : 0))*2);

    float acc[2][16][4];
    #pragma unroll
    for (int i = 0; i < 2; i++)
        #pragma unroll
        for (int j = 0; j < 16; j++)
            #pragma unroll
            for (int e = 0; e < 4; e++) acc[i][j][e] = 0.f;

    auto load_stage = [&](int s, int buf) {
        const int tap = (KWIN == 3) ? (s >> 3) : 0;
        const int cb  = (s & 7) * 32;
        // A: 2 chunks of 16B per thread (hi + lo each)
        #pragma unroll
        for (int h = 0; h < 2; h++) {
            const int c = tid*2 + h;
            const int row = c >> 2, kc = c & 3;
            const int src = tloc0 + row + tap - (KWIN >> 1);
            const bool valid = (KWIN == 1) || (src >= 0 && src < Tb);
            const size_t go = (size_t)(gseg + (valid ? src : 0))*256 + cb + kc*8;
            const uint32_t d = (uint32_t)((row*40 + kc*8)*2);
            cpa16(sb + SOFF_AHI(buf) + d, Ahi + go, valid ? 16 : 0);
            cpa16(sb + SOFF_ALO(buf) + d, Alo + go, valid ? 16 : 0);
        }
        // B: 4 chunks of 16B per thread (hi + lo each); n = tid
        #pragma unroll
        for (int h = 0; h < 4; h++) {
            const size_t go = (size_t)(n0 + tid)*K + s*32 + h*8;
            const uint32_t d = (uint32_t)((tid*40 + h*8)*2);
            cpa16(sb + SOFF_BHI(buf) + d, Whi + go, 16);
            cpa16(sb + SOFF_BLO(buf) + d, Wlo + go, 16);
        }
        asm volatile("cp.async.commit_group;");
    };

    auto compute_stage = [&](int buf) {
        const uint32_t sAh = sb + SOFF_AHI(buf) + aoff;
        const uint32_t sAl = sb + SOFF_ALO(buf) + aoff;
        const uint32_t sBh = sb + SOFF_BHI(buf) + boff;
        const uint32_t sBl = sb + SOFF_BLO(buf) + boff;
        #pragma unroll
        for (int q = 0; q < 2; q++) {
            uint32_t ah[2][4], al[2][4];
            ldm4(ah[0], sAh + q*32);
            ldm4(ah[1], sAh + 1280 + q*32);
            ldm4(al[0], sAl + q*32);
            ldm4(al[1], sAl + 1280 + q*32);
            #pragma unroll
            for (int p = 0; p < 8; p++) {
                uint32_t bh[4], bl[4];
                ldm4(bh, sBh + p*1280 + q*32);
                ldm4(bl, sBl + p*1280 + q*32);
                // term 1: ah*bh over 4 accs, then al*bh, then ah*bl (reuse dist 4)
                #pragma unroll
                for (int mt = 0; mt < 2; mt++) {
                    mma16816(acc[mt][2*p],   ah[mt], bh[0], bh[1]);
                    mma16816(acc[mt][2*p+1], ah[mt], bh[2], bh[3]);
                }
                #pragma unroll
                for (int mt = 0; mt < 2; mt++) {
                    mma16816(acc[mt][2*p],   al[mt], bh[0], bh[1]);
                    mma16816(acc[mt][2*p+1], al[mt], bh[2], bh[3]);
                }
                #pragma unroll
                for (int mt = 0; mt < 2; mt++) {
                    mma16816(acc[mt][2*p],   ah[mt], bl[0], bl[1]);
                    mma16816(acc[mt][2*p+1], ah[mt], bl[2], bl[3]);
                }
            }
        }
    };

    load_stage(0, 0);
    #pragma unroll 1
    for (int s = 0; s < NS; s++) {
        if (s + 1 < NS) {
            load_stage(s + 1, (s + 1) & 1);
            asm volatile("cp.async.wait_group 1;");
        } else {
            asm volatile("cp.async.wait_group 0;");
        }
        __syncthreads();
        compute_stage(s & 1);
        __syncthreads();
    }

    // ------------------ epilogue ------------------
    const int lid2 = lid & 3, lrow = lid >> 2;
    // bias(+relu) in place; accumulate LN stats per row-slot
    float s1[4] = {0.f,0.f,0.f,0.f}, s2[4] = {0.f,0.f,0.f,0.f};
    #pragma unroll
    for (int mt = 0; mt < 2; mt++)
        #pragma unroll
        for (int nt = 0; nt < 16; nt++) {
            const int c = n0 + wn*128 + nt*8 + lid2*2;
            const float b0 = bias[c], b1 = bias[c+1];
            float v0 = acc[mt][nt][0] + b0, v1 = acc[mt][nt][1] + b1;
            float v2 = acc[mt][nt][2] + b0, v3 = acc[mt][nt][3] + b1;
            if (LNORM) {
                v0 = fmaxf(v0,0.f); v1 = fmaxf(v1,0.f); v2 = fmaxf(v2,0.f); v3 = fmaxf(v3,0.f);
                s1[mt*2]   += v0 + v1;  s2[mt*2]   += v0*v0 + v1*v1;
                s1[mt*2+1] += v2 + v3;  s2[mt*2+1] += v2*v2 + v3*v3;
            }
            acc[mt][nt][0] = v0; acc[mt][nt][1] = v1; acc[mt][nt][2] = v2; acc[mt][nt][3] = v3;
        }

    float mean[4], rstd[4];
    if (LNORM) {
        #pragma unroll
        for (int sl = 0; sl < 4; sl++) {
            s1[sl] += __shfl_xor_sync(0xffffffffu, s1[sl], 1);
            s1[sl] += __shfl_xor_sync(0xffffffffu, s1[sl], 2);
            s2[sl] += __shfl_xor_sync(0xffffffffu, s2[sl], 1);
            s2[sl] += __shfl_xor_sync(0xffffffffu, s2[sl], 2);
        }
        float2* lnarr = (float2*)smc;   // 128 rows x 2 halves (A region free now)
        if (lid2 == 0) {
            #pragma unroll
            for (int sl = 0; sl < 4; sl++) {
                int r = wm*32 + (sl >> 1)*16 + (sl & 1)*8 + lrow;
                lnarr[r*2 + wn] = make_float2(s1[sl], s2[sl]);
            }
        }
        __syncthreads();
        #pragma unroll
        for (int sl = 0; sl < 4; sl++) {
            int r = wm*32 + (sl >> 1)*16 + (sl & 1)*8 + lrow;
            float2 pa = lnarr[r*2], pb = lnarr[r*2 + 1];
            float m = (pa.x + pb.x) * (1.f/256.f);
            float var = (pa.y + pb.y) * (1.f/256.f) - m*m;
            mean[sl] = m;
            rstd[sl] = rsqrtf(var + 1e-5f);
        }
    }

    const int ml = MASK ? mellen[bIdx] : 0;
    #pragma unroll
    for (int mt = 0; mt < 2; mt++) {
        const int r0 = row0 + wm*32 + mt*16 + lrow;
        const int r1 = r0 + 8;
        const bool m0 = MASK && ((r0 & (Tb-1)) >= ml);
        const bool m1 = MASK && ((r1 & (Tb-1)) >= ml);
        #pragma unroll
        for (int nt = 0; nt < 16; nt++) {
            const int c = n0 + wn*128 + nt*8 + lid2*2;
            float v0 = acc[mt][nt][0], v1 = acc[mt][nt][1];
            float v2 = acc[mt][nt][2], v3 = acc[mt][nt][3];
            if (LNORM) {
                const float g0 = gam[c], g1 = gam[c+1], e0 = bet[c], e1 = bet[c+1];
                v0 = (v0 - mean[mt*2])*rstd[mt*2]*g0 + e0;
                v1 = (v1 - mean[mt*2])*rstd[mt*2]*g1 + e1;
                v2 = (v2 - mean[mt*2+1])*rstd[mt*2+1]*g0 + e0;
                v3 = (v3 - mean[mt*2+1])*rstd[mt*2+1]*g1 + e1;
            }
            if (m0) { v0 = 0.f; v1 = 0.f; }
            if (m1) { v2 = 0.f; v3 = 0.f; }
            if (OUTBF) {
                bf16 h0,l0h,h1,l1h; split1(v0,h0,l0h); split1(v1,h1,l1h);
                *(uint32_t*)(Yh + (size_t)r0*Cout + c) =
                    (uint32_t)__bfloat16_as_ushort(h0) | ((uint32_t)__bfloat16_as_ushort(h1) << 16);
                *(uint32_t*)(Yl + (size_t)r0*Cout + c) =
                    (uint32_t)__bfloat16_as_ushort(l0h) | ((uint32_t)__bfloat16_as_ushort(l1h) << 16);
                bf16 h2,l2h,h3,l3h; split1(v2,h2,l2h); split1(v3,h3,l3h);
                *(uint32_t*)(Yh + (size_t)r1*Cout + c) =
                    (uint32_t)__bfloat16_as_ushort(h2) | ((uint32_t)__bfloat16_as_ushort(h3) << 16);
                *(uint32_t*)(Yl + (size_t)r1*Cout + c) =
                    (uint32_t)__bfloat16_as_ushort(l2h) | ((uint32_t)__bfloat16_as_ushort(l3h) << 16);
            } else {
                *(float2*)(Yf + (size_t)r0*Cout + c) = make_float2(v0, v1);
                *(float2*)(Yf + (size_t)r1*Cout + c) = make_float2(v2, v3);
            }
        }
    }
}

// ---------------- duration linear head ----------------------------------------
__global__ void dp_linear(const float* __restrict__ H, const float* __restrict__ lw,
                          const float* __restrict__ lb, float* __restrict__ outp) {
    int row = blockIdx.x;
    int t = threadIdx.x;
    float v = H[(size_t)row*FF + t] * lw[t];
    #pragma unroll
    for (int o = 16; o; o >>= 1) v += __shfl_down_sync(0xffffffffu, v, o);
    __shared__ float s[8];
    if ((t & 31) == 0) s[t >> 5] = v;
    __syncthreads();
    if (t == 0) {
        float a = 0.f;
        #pragma unroll
        for (int i = 0; i < 8; i++) a += s[i];
        outp[row] = a + lb[0];
    }
}

// ---------------- pitch head: dot + mask + bucketize + emb add + split -------
__global__ void pitch_kernel(const float* __restrict__ H, const float* __restrict__ lw,
                             const float* __restrict__ lb, const float* __restrict__ bins,
                             const float* __restrict__ emb, const int* __restrict__ mellen,
                             float* __restrict__ pout) {
    int row = blockIdx.x;
    int b = row >> 11;
    int m = row & (MAXMEL - 1);
    int t = threadIdx.x;
    float v = H[(size_t)row*FF + t] * lw[t];
    #pragma unroll
    for (int o = 16; o; o >>= 1) v += __shfl_down_sync(0xffffffffu, v, o);
    __shared__ float s[8];
    __shared__ int bkt;
    if ((t & 31) == 0) s[t >> 5] = v;
    __syncthreads();
    if (t == 0) {
        float a = 0.f;
        #pragma unroll
        for (int i = 0; i < 8; i++) a += s[i];
        a += lb[0];
        if (m >= mellen[b]) a = 0.f;
        pout[row] = a;
        int lo = 0, hi = NBINS - 1;
        while (lo < hi) { int mid = (lo + hi) >> 1; if (bins[mid] < a) lo = mid + 1; else hi = mid; }
        bkt = lo;
    }
    __syncthreads();
    float xv = g_bufX[(size_t)row*DD + t] + emb[(size_t)bkt*DD + t];
    bf16 h, l; split1(xv, h, l);
    g_xh[(size_t)row*DD + t] = h;
    g_xl[(size_t)row*DD + t] = l;
}

// ------------------------------- launch ----------------------------------------
extern "C" void kernel_launch(void* const* d_in, const int* in_sizes, int n_in,
                              void* d_out, int out_size) {
    const float* ling   = (const float*)d_in[0];
    const int*   dur    = (const int*)  d_in[1];
    const float* dp_w1  = (const float*)d_in[3];
    const float* dp_b1  = (const float*)d_in[4];
    const float* dp_g1  = (const float*)d_in[5];
    const float* dp_be1 = (const float*)d_in[6];
    const float* dp_w2  = (const float*)d_in[7];
    const float* dp_b2  = (const float*)d_in[8];
    const float* dp_g2  = (const float*)d_in[9];
    const float* dp_be2 = (const float*)d_in[10];
    const float* dp_lw  = (const float*)d_in[11];
    const float* dp_lb  = (const float*)d_in[12];
    const float* pp_w1  = (const float*)d_in[13];
    const float* pp_b1  = (const float*)d_in[14];
    const float* pp_g1  = (const float*)d_in[15];
    const float* pp_be1 = (const float*)d_in[16];
    const float* pp_w2  = (const float*)d_in[17];
    const float* pp_b2  = (const float*)d_in[18];
    const float* pp_g2  = (const float*)d_in[19];
    const float* pp_be2 = (const float*)d_in[20];
    const float* pp_lw  = (const float*)d_in[21];
    const float* pp_lb  = (const float*)d_in[22];
    const float* bins   = (const float*)d_in[23];
    const float* emb    = (const float*)d_in[24];
    const float* proj_w = (const float*)d_in[25];
    const float* proj_b = (const float*)d_in[26];

    float* out = (float*)d_out;

    float *bufX, *bufB;
    bf16 *wh, *wl, *xh, *xl, *yh, *yl, *dh, *dl;
    int *idxb, *mellen;
    cudaGetSymbolAddress((void**)&bufX,   g_bufX);
    cudaGetSymbolAddress((void**)&bufB,   g_bufB);
    cudaGetSymbolAddress((void**)&wh,     g_wh);
    cudaGetSymbolAddress((void**)&wl,     g_wl);
    cudaGetSymbolAddress((void**)&xh,     g_xh);
    cudaGetSymbolAddress((void**)&xl,     g_xl);
    cudaGetSymbolAddress((void**)&yh,     g_yh);
    cudaGetSymbolAddress((void**)&yl,     g_yl);
    cudaGetSymbolAddress((void**)&dh,     g_dh);
    cudaGetSymbolAddress((void**)&dl,     g_dl);
    cudaGetSymbolAddress((void**)&idxb,   g_idx);
    cudaGetSymbolAddress((void**)&mellen, g_mellen);

    cudaFuncSetAttribute(gemm_big<3,true,false,true,11>,  cudaFuncAttributeMaxDynamicSharedMemorySize, SM_TOTAL);
    cudaFuncSetAttribute(gemm_big<3,true,false,false,11>, cudaFuncAttributeMaxDynamicSharedMemorySize, SM_TOTAL);
    cudaFuncSetAttribute(gemm_big<1,false,true,false,11>, cudaFuncAttributeMaxDynamicSharedMemorySize, SM_TOTAL);
    cudaFuncSetAttribute(gemm_big<3,true,false,true,8>,   cudaFuncAttributeMaxDynamicSharedMemorySize, SM_TOTAL);
    cudaFuncSetAttribute(gemm_big<3,true,false,false,8>,  cudaFuncAttributeMaxDynamicSharedMemorySize, SM_TOTAL);

    // ---- launch order chosen so the big pitch conv1 GEMM is launch #6 (ncu -s 5) ----
    length_reg<<<BB, TSLEN>>>(dur, idxb, mellen, out + MEL_OFF);                 // 1
    gather_x<<<BB*MAXMEL, 64>>>(ling, idxb, mellen);                             // 2
    prep_w_conv_bf<<<768, 256>>>(pp_w1, wh + 2*WCONV, wl + 2*WCONV);             // 3
    prep_w_conv_bf<<<768, 256>>>(pp_w2, wh + 3*WCONV, wl + 3*WCONV);             // 4
    prep_w_conv_bf<<<768, 256>>>(dp_w1, wh + 0*WCONV, wl + 0*WCONV);             // 5

    // 6: pitch conv1 (rows=65536) -> yh/yl with fused relu+LN+split
    gemm_big<3,true,false,true,11><<<dim3(512,1), 256, SM_TOTAL>>>(
        xh, xl, wh + 2*WCONV, wl + 2*WCONV, pp_b1, pp_g1, pp_be1,
        nullptr, yh, yl, 256, nullptr);
    // 7: pitch conv2 -> bufB fp32 (fused relu+LN)
    gemm_big<3,true,false,false,11><<<dim3(512,1), 256, SM_TOTAL>>>(
        yh, yl, wh + 3*WCONV, wl + 3*WCONV, pp_b2, pp_g2, pp_be2,
        bufB, nullptr, nullptr, 256, nullptr);
    // 8: pitch head (updates xh/xl with emb)
    pitch_kernel<<<BB*MAXMEL, 256>>>(bufB, pp_lw, pp_lb, bins, emb, mellen, out + PITCH_OFF);
    // 9: proj weight prep
    prep_w_proj_bf<<<512, 256>>>(proj_w, wh + 4*WCONV, wl + 4*WCONV);
    // 10: final projection -> d_out (masked)
    gemm_big<1,false,true,false,11><<<dim3(512,2), 256, SM_TOTAL>>>(
        xh, xl, wh + 4*WCONV, wl + 4*WCONV, proj_b, nullptr, nullptr,
        out, nullptr, nullptr, 512, mellen);

    // ---- duration predictor (rows = 8192) ----
    split_f32<<<(BB*TSLEN*DD/4)/256, 256>>>(ling, dh, dl);                       // 11
    prep_w_conv_bf<<<768, 256>>>(dp_w2, wh + 1*WCONV, wl + 1*WCONV);             // 12
    gemm_big<3,true,false,true,8><<<dim3(64,1), 256, SM_TOTAL>>>(                 // 13
        dh, dl, wh + 0*WCONV, wl + 0*WCONV, dp_b1, dp_g1, dp_be1,
        nullptr, yh, yl, 256, nullptr);
    gemm_big<3,true,false,false,8><<<dim3(64,1), 256, SM_TOTAL>>>(                // 14
        yh, yl, wh + 1*WCONV, wl + 1*WCONV, dp_b2, dp_g2, dp_be2,
        bufB, nullptr, nullptr, 256, nullptr);
    dp_linear<<<BB*TSLEN, 256>>>(bufB, dp_lw, dp_lb, out + LOGDUR_OFF);          // 15
}

// round 6
// speedup vs baseline: 1.3156x; 1.3156x over previous
#include <cuda_runtime.h>
#include <cuda_bf16.h>
#include <math.h>
#include <stdint.h>

#define BB      32
#define TSLEN   256
#define DD      256
#define FF      256
#define MAXMEL  2048
#define NBINS   256

#define OUT_ELEMS   (BB*MAXMEL*2*DD)
#define LOGDUR_OFF  OUT_ELEMS
#define PITCH_OFF   (LOGDUR_OFF + BB*TSLEN)
#define MEL_OFF     (PITCH_OFF + BB*MAXMEL)

#define WCONV (256*768)
#define WPROJ (512*256)

typedef __nv_bfloat16 bf16;

// ---------------- scratch (static device globals; no allocation) -------------
__device__ float g_bufX[BB*MAXMEL*DD];          // gathered fp32 (for emb add)
__device__ float g_bufA[BB*MAXMEL*FF];          // conv1 out fp32
__device__ float g_bufB[BB*MAXMEL*FF];          // conv2 out fp32
__device__ bf16  g_xh[BB*MAXMEL*DD];            // pitch/proj activation hi
__device__ bf16  g_xl[BB*MAXMEL*DD];
__device__ bf16  g_yh[BB*MAXMEL*FF];            // conv1->conv2 hi
__device__ bf16  g_yl[BB*MAXMEL*FF];
__device__ bf16  g_dh[BB*TSLEN*DD];             // dur-path ling hi
__device__ bf16  g_dl[BB*TSLEN*DD];
__device__ bf16  g_wh[4*WCONV + WPROJ];
__device__ bf16  g_wl[4*WCONV + WPROJ];
__device__ int   g_idx[BB*MAXMEL];
__device__ int   g_mellen[BB];

// ---------------- helpers -----------------------------------------------------
__device__ __forceinline__ void cpa16(uint32_t d, const void* s, int sz) {
    asm volatile("cp.async.ca.shared.global [%0], [%1], 16, %2;" :: "r"(d), "l"(s), "r"(sz));
}
__device__ __forceinline__ void ldm4(uint32_t* r, uint32_t a) {
    asm volatile("ldmatrix.sync.aligned.m8n8.x4.shared.b16 {%0,%1,%2,%3}, [%4];"
        : "=r"(r[0]), "=r"(r[1]), "=r"(r[2]), "=r"(r[3]) : "r"(a));
}
__device__ __forceinline__ void mma16816(float* c, const uint32_t* a, uint32_t b0, uint32_t b1) {
    asm volatile(
        "mma.sync.aligned.m16n8k16.row.col.f32.bf16.bf16.f32 "
        "{%0,%1,%2,%3}, {%4,%5,%6,%7}, {%8,%9}, {%0,%1,%2,%3};"
        : "+f"(c[0]), "+f"(c[1]), "+f"(c[2]), "+f"(c[3])
        : "r"(a[0]), "r"(a[1]), "r"(a[2]), "r"(a[3]), "r"(b0), "r"(b1));
}
__device__ __forceinline__ void split1(float x, bf16& h, bf16& l) {
    h = __float2bfloat16_rn(x);
    l = __float2bfloat16_rn(x - __bfloat162float(h));
}

// SMEM layout (R4): 8 tiles of 128 x 40 halfwords (10240 B)
#define TILEB 10240
#define SOFF_AHI(b) ((b)*TILEB)
#define SOFF_ALO(b) (2*TILEB + (b)*TILEB)
#define SOFF_BHI(b) (4*TILEB + (b)*TILEB)
#define SOFF_BLO(b) (6*TILEB + (b)*TILEB)
#define SM_TOTAL (8*TILEB)

// ---------------- merged weight prep ------------------------------------------
__global__ void prep_all(const float* __restrict__ dp_w1, const float* __restrict__ dp_w2,
                         const float* __restrict__ pp_w1, const float* __restrict__ pp_w2,
                         const float* __restrict__ proj_w,
                         bf16* __restrict__ H, bf16* __restrict__ L) {
    int bid = blockIdx.x;
    if (bid < 3072) {                       // conv weights
        int slot = bid >> 9;                // bid / 768... careful: 768 blocks per slot
        slot = bid / 768;
        const float* W = (slot == 0) ? dp_w1 : (slot == 1) ? dp_w2 : (slot == 2) ? pp_w1 : pp_w2;
        int o = (bid - slot*768) * 256 + threadIdx.x;    // < 196608
        int f = o / 768;
        int r = o - f * 768;
        int tap = r >> 8;
        int c = r & 255;
        float w = W[f*768 + c*3 + tap];
        bf16 h, l; split1(w, h, l);
        H[slot*WCONV + o] = h; L[slot*WCONV + o] = l;
    } else {                                 // proj weight
        int o = (bid - 3072) * 256 + threadIdx.x;        // < 131072
        int n = o >> 8;
        int k = o & 255;
        float w = proj_w[k*512 + n];
        bf16 h, l; split1(w, h, l);
        H[4*WCONV + o] = h; L[4*WCONV + o] = l;
    }
}

// ---------------- split fp32 activations -> bf16 hi/lo -----------------------
__global__ void split_f32(const float* __restrict__ in, bf16* __restrict__ hi,
                          bf16* __restrict__ lo) {
    int i = blockIdx.x * 256 + threadIdx.x;
    float4 v = ((const float4*)in)[i];
    bf16 h0,h1,h2,h3, l0,l1,l2,l3;
    split1(v.x,h0,l0); split1(v.y,h1,l1); split1(v.z,h2,l2); split1(v.w,h3,l3);
    ((ushort4*)hi)[i] = make_ushort4(__bfloat16_as_ushort(h0), __bfloat16_as_ushort(h1),
                                     __bfloat16_as_ushort(h2), __bfloat16_as_ushort(h3));
    ((ushort4*)lo)[i] = make_ushort4(__bfloat16_as_ushort(l0), __bfloat16_as_ushort(l1),
                                     __bfloat16_as_ushort(l2), __bfloat16_as_ushort(l3));
}

// ---------------- length regulator -------------------------------------------
__global__ void length_reg(const int* __restrict__ dur, int* __restrict__ idxb,
                           int* __restrict__ mellen, float* __restrict__ out_mel) {
    __shared__ int cum[TSLEN];
    int b = blockIdx.x;
    int t = threadIdx.x;
    cum[t] = dur[b*TSLEN + t];
    __syncthreads();
    for (int off = 1; off < TSLEN; off <<= 1) {
        int v = (t >= off) ? cum[t - off] : 0;
        __syncthreads();
        cum[t] += v;
        __syncthreads();
    }
    int ml = min(cum[TSLEN-1], MAXMEL);
    if (t == 0) { mellen[b] = ml; out_mel[b] = (float)ml; }
    for (int m = t; m < MAXMEL; m += TSLEN) {
        int lo = 0, hi = TSLEN;
        while (lo < hi) { int mid = (lo + hi) >> 1; if (cum[mid] <= m) lo = mid + 1; else hi = mid; }
        idxb[b*MAXMEL + m] = min(lo, TSLEN - 1);
    }
}

// ---------------- gather expanded x + fused hi/lo split ----------------------
__global__ void gather_x(const float* __restrict__ ling, const int* __restrict__ idxb,
                         const int* __restrict__ mellen) {
    int row = blockIdx.x;
    int b = row >> 11;
    int m = row & (MAXMEL - 1);
    bool masked = (m >= mellen[b]);
    int src = idxb[row];
    const float4* s = (const float4*)(ling + ((size_t)b*TSLEN + src)*DD);
    float4 v = masked ? make_float4(0.f,0.f,0.f,0.f) : s[threadIdx.x];
    ((float4*)(g_bufX + (size_t)row*DD))[threadIdx.x] = v;
    bf16 h0,h1,h2,h3, l0,l1,l2,l3;
    split1(v.x,h0,l0); split1(v.y,h1,l1); split1(v.z,h2,l2); split1(v.w,h3,l3);
    ((ushort4*)(g_xh + (size_t)row*DD))[threadIdx.x] =
        make_ushort4(__bfloat16_as_ushort(h0), __bfloat16_as_ushort(h1),
                     __bfloat16_as_ushort(h2), __bfloat16_as_ushort(h3));
    ((ushort4*)(g_xl + (size_t)row*DD))[threadIdx.x] =
        make_ushort4(__bfloat16_as_ushort(l0), __bfloat16_as_ushort(l1),
                     __bfloat16_as_ushort(l2), __bfloat16_as_ushort(l3));
}

// ---------------- HMMA GEMM (identical to R4): 128x128 tile, 2 CTA/SM --------
template<int KWIN, bool RELU, bool MASK, int TSHIFT>
__global__ __launch_bounds__(256, 2)
void gemm_mma(const bf16* __restrict__ Ahi, const bf16* __restrict__ Alo,
              const bf16* __restrict__ Whi, const bf16* __restrict__ Wlo,
              const float* __restrict__ bias, float* __restrict__ Y, int Cout,
              const int* __restrict__ mellen) {
    constexpr int Tb = 1 << TSHIFT;
    constexpr int NS = KWIN * 8;
    constexpr int K  = KWIN * 256;
    extern __shared__ char smc[];
    const uint32_t sb = (uint32_t)__cvta_generic_to_shared(smc);

    const int tid = threadIdx.x;
    const int wid = tid >> 5, lid = tid & 31;
    const int wm = wid >> 1, wn = wid & 1;
    const int row0 = blockIdx.x * 128;
    const int n0   = blockIdx.y * 128;
    const int tloc0 = row0 & (Tb - 1);
    const int gseg  = row0 - tloc0;
    const int bIdx  = row0 >> TSHIFT;

    const uint32_t aoff = (uint32_t)(wm*2560 + ((lid & 15)*40 + ((lid & 16) ? 8 : 0))*2);
    const uint32_t boff = (uint32_t)(wn*5120 + (((lid & 7) + ((lid & 16) ? 8 : 0))*40
                                               + ((lid & 8) ? 8 : 0))*2);

    const int r0c = tid >> 2,          kc0 = tid & 3;
    const int r1c = (tid + 256) >> 2,  kc1 = (tid + 256) & 3;

    float acc[2][8][4];
    #pragma unroll
    for (int i = 0; i < 2; i++)
        #pragma unroll
        for (int j = 0; j < 8; j++)
            #pragma unroll
            for (int e = 0; e < 4; e++) acc[i][j][e] = 0.f;

    auto load_stage = [&](int s, int buf) {
        const int tap = (KWIN == 3) ? (s >> 3) : 0;
        const int cb  = (s & 7) * 32;
        #pragma unroll
        for (int h = 0; h < 2; h++) {
            const int row = h ? r1c : r0c;
            const int kc  = h ? kc1 : kc0;
            const int src = tloc0 + row + tap - (KWIN >> 1);
            const bool valid = (KWIN == 1) || (src >= 0 && src < Tb);
            const size_t go = (size_t)(gseg + (valid ? src : 0))*256 + cb + kc*8;
            const uint32_t d = (uint32_t)((row*40 + kc*8)*2);
            cpa16(sb + SOFF_AHI(buf) + d, Ahi + go, valid ? 16 : 0);
            cpa16(sb + SOFF_ALO(buf) + d, Alo + go, valid ? 16 : 0);
        }
        #pragma unroll
        for (int h = 0; h < 2; h++) {
            const int row = h ? r1c : r0c;
            const int kc  = h ? kc1 : kc0;
            const size_t go = (size_t)(n0 + row)*K + s*32 + kc*8;
            const uint32_t d = (uint32_t)((row*40 + kc*8)*2);
            cpa16(sb + SOFF_BHI(buf) + d, Whi + go, 16);
            cpa16(sb + SOFF_BLO(buf) + d, Wlo + go, 16);
        }
        asm volatile("cp.async.commit_group;");
    };

    auto compute_stage = [&](int buf) {
        const uint32_t sAh = sb + SOFF_AHI(buf) + aoff;
        const uint32_t sAl = sb + SOFF_ALO(buf) + aoff;
        const uint32_t sBh = sb + SOFF_BHI(buf) + boff;
        const uint32_t sBl = sb + SOFF_BLO(buf) + boff;
        #pragma unroll
        for (int q = 0; q < 2; q++) {
            uint32_t ah[2][4], bh[4][4];
            ldm4(ah[0], sAh + q*32);
            ldm4(ah[1], sAh + 1280 + q*32);
            #pragma unroll
            for (int p = 0; p < 4; p++) ldm4(bh[p], sBh + p*1280 + q*32);
            #pragma unroll
            for (int mt = 0; mt < 2; mt++)
                #pragma unroll
                for (int p = 0; p < 4; p++) {
                    mma16816(acc[mt][2*p],   ah[mt], bh[p][0], bh[p][1]);
                    mma16816(acc[mt][2*p+1], ah[mt], bh[p][2], bh[p][3]);
                }
            uint32_t al[2][4];
            ldm4(al[0], sAl + q*32);
            ldm4(al[1], sAl + 1280 + q*32);
            #pragma unroll
            for (int mt = 0; mt < 2; mt++)
                #pragma unroll
                for (int p = 0; p < 4; p++) {
                    mma16816(acc[mt][2*p],   al[mt], bh[p][0], bh[p][1]);
                    mma16816(acc[mt][2*p+1], al[mt], bh[p][2], bh[p][3]);
                }
            uint32_t bl[4][4];
            #pragma unroll
            for (int p = 0; p < 4; p++) ldm4(bl[p], sBl + p*1280 + q*32);
            #pragma unroll
            for (int mt = 0; mt < 2; mt++)
                #pragma unroll
                for (int p = 0; p < 4; p++) {
                    mma16816(acc[mt][2*p],   ah[mt], bl[p][0], bl[p][1]);
                    mma16816(acc[mt][2*p+1], ah[mt], bl[p][2], bl[p][3]);
                }
        }
    };

    load_stage(0, 0);
    #pragma unroll 1
    for (int s = 0; s < NS; s++) {
        if (s + 1 < NS) {
            load_stage(s + 1, (s + 1) & 1);
            asm volatile("cp.async.wait_group 1;");
        } else {
            asm volatile("cp.async.wait_group 0;");
        }
        __syncthreads();
        compute_stage(s & 1);
        __syncthreads();
    }

    const int mrow = row0 + wm*32;
    const int ncol = n0 + wn*64;
    const int ml = MASK ? mellen[bIdx] : 0;
    #pragma unroll
    for (int mt = 0; mt < 2; mt++) {
        const int r = mrow + mt*16 + (lid >> 2);
        const bool m0 = MASK && ((r     & (Tb-1)) >= ml);
        const bool m1 = MASK && (((r+8) & (Tb-1)) >= ml);
        #pragma unroll
        for (int nt = 0; nt < 8; nt++) {
            const int c = ncol + nt*8 + (lid & 3)*2;
            const float bb0 = bias[c], bb1 = bias[c+1];
            float v0 = acc[mt][nt][0] + bb0, v1 = acc[mt][nt][1] + bb1;
            float v2 = acc[mt][nt][2] + bb0, v3 = acc[mt][nt][3] + bb1;
            if (RELU) { v0 = fmaxf(v0,0.f); v1 = fmaxf(v1,0.f); v2 = fmaxf(v2,0.f); v3 = fmaxf(v3,0.f); }
            if (m0) { v0 = 0.f; v1 = 0.f; }
            if (m1) { v2 = 0.f; v3 = 0.f; }
            *(float2*)(Y + (size_t)r*Cout + c)     = make_float2(v0, v1);
            *(float2*)(Y + (size_t)(r+8)*Cout + c) = make_float2(v2, v3);
        }
    }
}

// ---------------- LayerNorm (split output, conv1 -> conv2) --------------------
__global__ void layernorm_split(const float* __restrict__ H, const float* __restrict__ g,
                                const float* __restrict__ be,
                                bf16* __restrict__ hi, bf16* __restrict__ lo) {
    int row = blockIdx.x;
    int t = threadIdx.x;
    float x = H[(size_t)row*FF + t];
    float v1 = x, v2 = x*x;
    #pragma unroll
    for (int o = 16; o; o >>= 1) {
        v1 += __shfl_down_sync(0xffffffffu, v1, o);
        v2 += __shfl_down_sync(0xffffffffu, v2, o);
    }
    __shared__ float s1[8], s2[8];
    __shared__ float mean, rstd;
    int w = t >> 5, l = t & 31;
    if (l == 0) { s1[w] = v1; s2[w] = v2; }
    __syncthreads();
    if (t == 0) {
        float a = 0.f, q = 0.f;
        #pragma unroll
        for (int i = 0; i < 8; i++) { a += s1[i]; q += s2[i]; }
        float m = a * (1.f/256.f);
        float var = q * (1.f/256.f) - m*m;
        mean = m;
        rstd = rsqrtf(var + 1e-5f);
    }
    __syncthreads();
    float y = (x - mean) * rstd * g[t] + be[t];
    bf16 h, ll; split1(y, h, ll);
    hi[(size_t)row*FF + t] = h;
    lo[(size_t)row*FF + t] = ll;
}

// ---------------- fused LN + duration linear head -----------------------------
__global__ void dp_head(const float* __restrict__ H, const float* __restrict__ g,
                        const float* __restrict__ be, const float* __restrict__ lw,
                        const float* __restrict__ lb, float* __restrict__ outp) {
    int row = blockIdx.x;
    int t = threadIdx.x;
    float x = H[(size_t)row*FF + t];
    float v1 = x, v2 = x*x;
    #pragma unroll
    for (int o = 16; o; o >>= 1) {
        v1 += __shfl_down_sync(0xffffffffu, v1, o);
        v2 += __shfl_down_sync(0xffffffffu, v2, o);
    }
    __shared__ float s1[8], s2[8];
    __shared__ float mean, rstd;
    int w = t >> 5, l = t & 31;
    if (l == 0) { s1[w] = v1; s2[w] = v2; }
    __syncthreads();
    if (t == 0) {
        float a = 0.f, q = 0.f;
        #pragma unroll
        for (int i = 0; i < 8; i++) { a += s1[i]; q += s2[i]; }
        float m = a * (1.f/256.f);
        float var = q * (1.f/256.f) - m*m;
        mean = m;
        rstd = rsqrtf(var + 1e-5f);
    }
    __syncthreads();
    float y = (x - mean) * rstd * g[t] + be[t];
    float v = y * lw[t];
    #pragma unroll
    for (int o = 16; o; o >>= 1) v += __shfl_down_sync(0xffffffffu, v, o);
    if (l == 0) s1[w] = v;
    __syncthreads();
    if (t == 0) {
        float a = 0.f;
        #pragma unroll
        for (int i = 0; i < 8; i++) a += s1[i];
        outp[row] = a + lb[0];
    }
}

// ---------------- fused LN + pitch head ---------------------------------------
__global__ void pitch_head(const float* __restrict__ H, const float* __restrict__ g,
                           const float* __restrict__ be, const float* __restrict__ lw,
                           const float* __restrict__ lb, const float* __restrict__ bins,
                           const float* __restrict__ emb, const int* __restrict__ mellen,
                           float* __restrict__ pout) {
    int row = blockIdx.x;
    int b = row >> 11;
    int m = row & (MAXMEL - 1);
    int t = threadIdx.x;
    float x = H[(size_t)row*FF + t];
    float v1 = x, v2 = x*x;
    #pragma unroll
    for (int o = 16; o; o >>= 1) {
        v1 += __shfl_down_sync(0xffffffffu, v1, o);
        v2 += __shfl_down_sync(0xffffffffu, v2, o);
    }
    __shared__ float s1[8], s2[8];
    __shared__ float mean, rstd;
    __shared__ int bkt;
    int w = t >> 5, l = t & 31;
    if (l == 0) { s1[w] = v1; s2[w] = v2; }
    __syncthreads();
    if (t == 0) {
        float a = 0.f, q = 0.f;
        #pragma unroll
        for (int i = 0; i < 8; i++) { a += s1[i]; q += s2[i]; }
        float mm = a * (1.f/256.f);
        float var = q * (1.f/256.f) - mm*mm;
        mean = mm;
        rstd = rsqrtf(var + 1e-5f);
    }
    __syncthreads();
    float y = (x - mean) * rstd * g[t] + be[t];
    float v = y * lw[t];
    #pragma unroll
    for (int o = 16; o; o >>= 1) v += __shfl_down_sync(0xffffffffu, v, o);
    if (l == 0) s1[w] = v;
    __syncthreads();
    if (t == 0) {
        float a = 0.f;
        #pragma unroll
        for (int i = 0; i < 8; i++) a += s1[i];
        a += lb[0];
        if (m >= mellen[b]) a = 0.f;       // mask BEFORE bucketize (matches ref)
        pout[row] = a;
        int lo = 0, hi = NBINS - 1;
        while (lo < hi) { int mid = (lo + hi) >> 1; if (bins[mid] < a) lo = mid + 1; else hi = mid; }
        bkt = lo;
    }
    __syncthreads();
    float xv = g_bufX[(size_t)row*DD + t] + emb[(size_t)bkt*DD + t];
    bf16 h, ll; split1(xv, h, ll);
    g_xh[(size_t)row*DD + t] = h;
    g_xl[(size_t)row*DD + t] = ll;
}

// ------------------------------- launch ----------------------------------------
extern "C" void kernel_launch(void* const* d_in, const int* in_sizes, int n_in,
                              void* d_out, int out_size) {
    const float* ling   = (const float*)d_in[0];
    const int*   dur    = (const int*)  d_in[1];
    const float* dp_w1  = (const float*)d_in[3];
    const float* dp_b1  = (const float*)d_in[4];
    const float* dp_g1  = (const float*)d_in[5];
    const float* dp_be1 = (const float*)d_in[6];
    const float* dp_w2  = (const float*)d_in[7];
    const float* dp_b2  = (const float*)d_in[8];
    const float* dp_g2  = (const float*)d_in[9];
    const float* dp_be2 = (const float*)d_in[10];
    const float* dp_lw  = (const float*)d_in[11];
    const float* dp_lb  = (const float*)d_in[12];
    const float* pp_w1  = (const float*)d_in[13];
    const float* pp_b1  = (const float*)d_in[14];
    const float* pp_g1  = (const float*)d_in[15];
    const float* pp_be1 = (const float*)d_in[16];
    const float* pp_w2  = (const float*)d_in[17];
    const float* pp_b2  = (const float*)d_in[18];
    const float* pp_g2  = (const float*)d_in[19];
    const float* pp_be2 = (const float*)d_in[20];
    const float* pp_lw  = (const float*)d_in[21];
    const float* pp_lb  = (const float*)d_in[22];
    const float* bins   = (const float*)d_in[23];
    const float* emb    = (const float*)d_in[24];
    const float* proj_w = (const float*)d_in[25];
    const float* proj_b = (const float*)d_in[26];

    float* out = (float*)d_out;

    float *bufA, *bufB;
    bf16 *wh, *wl, *xh, *xl, *yh, *yl, *dh, *dl;
    int *idxb, *mellen;
    cudaGetSymbolAddress((void**)&bufA,   g_bufA);
    cudaGetSymbolAddress((void**)&bufB,   g_bufB);
    cudaGetSymbolAddress((void**)&wh,     g_wh);
    cudaGetSymbolAddress((void**)&wl,     g_wl);
    cudaGetSymbolAddress((void**)&xh,     g_xh);
    cudaGetSymbolAddress((void**)&xl,     g_xl);
    cudaGetSymbolAddress((void**)&yh,     g_yh);
    cudaGetSymbolAddress((void**)&yl,     g_yl);
    cudaGetSymbolAddress((void**)&dh,     g_dh);
    cudaGetSymbolAddress((void**)&dl,     g_dl);
    cudaGetSymbolAddress((void**)&idxb,   g_idx);
    cudaGetSymbolAddress((void**)&mellen, g_mellen);

    cudaFuncSetAttribute(gemm_mma<3,true,false,8>,  cudaFuncAttributeMaxDynamicSharedMemorySize, SM_TOTAL);
    cudaFuncSetAttribute(gemm_mma<3,true,false,11>, cudaFuncAttributeMaxDynamicSharedMemorySize, SM_TOTAL);
    cudaFuncSetAttribute(gemm_mma<1,false,true,11>, cudaFuncAttributeMaxDynamicSharedMemorySize, SM_TOTAL);

    // launch order: #4 (my numbering) = big pitch conv1 GEMM -> ncu capture
    length_reg<<<BB, TSLEN>>>(dur, idxb, mellen, out + MEL_OFF);                 // 1
    gather_x<<<BB*MAXMEL, 64>>>(ling, idxb, mellen);                             // 2
    prep_all<<<3584, 256>>>(dp_w1, dp_w2, pp_w1, pp_w2, proj_w, wh, wl);         // 3

    // ---- pitch predictor (rows = 65536) ----
    gemm_mma<3,true,false,11><<<dim3(512,2), 256, SM_TOTAL>>>(                    // 4 <- ncu
        xh, xl, wh + 2*WCONV, wl + 2*WCONV, pp_b1, bufA, 256, nullptr);
    layernorm_split<<<BB*MAXMEL, 256>>>(bufA, pp_g1, pp_be1, yh, yl);             // 5
    gemm_mma<3,true,false,11><<<dim3(512,2), 256, SM_TOTAL>>>(                    // 6
        yh, yl, wh + 3*WCONV, wl + 3*WCONV, pp_b2, bufB, 256, nullptr);
    pitch_head<<<BB*MAXMEL, 256>>>(bufB, pp_g2, pp_be2, pp_lw, pp_lb,             // 7
        bins, emb, mellen, out + PITCH_OFF);

    // ---- final projection D -> 2D, masked, into d_out ----
    gemm_mma<1,false,true,11><<<dim3(512,4), 256, SM_TOTAL>>>(                    // 8
        xh, xl, wh + 4*WCONV, wl + 4*WCONV, proj_b, out, 512, mellen);

    // ---- duration predictor (rows = 8192) ----
    split_f32<<<(BB*TSLEN*DD/4)/256, 256>>>(ling, dh, dl);                        // 9
    gemm_mma<3,true,false,8><<<dim3(64,2), 256, SM_TOTAL>>>(                      // 10
        dh, dl, wh + 0*WCONV, wl + 0*WCONV, dp_b1, bufA, 256, nullptr);
    layernorm_split<<<BB*TSLEN, 256>>>(bufA, dp_g1, dp_be1, dh, dl);              // 11
    gemm_mma<3,true,false,8><<<dim3(64,2), 256, SM_TOTAL>>>(                      // 12
        dh, dl, wh + 1*WCONV, wl + 1*WCONV, dp_b2, bufB, 256, nullptr);
    dp_head<<<BB*TSLEN, 256>>>(bufB, dp_g2, dp_be2, dp_lw, dp_lb, out + LOGDUR_OFF); // 13
}

// round 7
// speedup vs baseline: 1.4042x; 1.0673x over previous
#include <cuda_runtime.h>
#include <cuda_bf16.h>
#include <math.h>
#include <stdint.h>

#define BB      32
#define TSLEN   256
#define DD      256
#define FF      256
#define MAXMEL  2048
#define NBINS   256

#define OUT_ELEMS   (BB*MAXMEL*2*DD)
#define LOGDUR_OFF  OUT_ELEMS
#define PITCH_OFF   (LOGDUR_OFF + BB*TSLEN)
#define MEL_OFF     (PITCH_OFF + BB*MAXMEL)

#define WCONV (256*768)
#define WPROJ (512*256)

typedef __nv_bfloat16 bf16;

// ---------------- scratch -------------------------------------------------------
__device__ float g_bufX[BB*MAXMEL*DD];          // gathered fp32 (for emb add)
__device__ float g_bufA[BB*MAXMEL*FF];          // pitch conv out fp32
__device__ float g_bufB[BB*MAXMEL*FF];          // dur conv out fp32 (small slice used)
__device__ bf16  g_xh[BB*MAXMEL*DD];            // pitch/proj activation hi
__device__ bf16  g_xl[BB*MAXMEL*DD];
__device__ bf16  g_yh[BB*MAXMEL*FF];            // pitch conv1->conv2 hi
__device__ bf16  g_yl[BB*MAXMEL*FF];
__device__ bf16  g_dh[BB*TSLEN*DD];             // dur-path activations hi
__device__ bf16  g_dl[BB*TSLEN*DD];
__device__ bf16  g_wh[4*WCONV + WPROJ];
__device__ bf16  g_wl[4*WCONV + WPROJ];
__device__ int   g_idx[BB*MAXMEL];
__device__ int   g_mellen[BB];

// ---------------- helpers -------------------------------------------------------
__device__ __forceinline__ void cpa16(uint32_t d, const void* s, int sz) {
    asm volatile("cp.async.ca.shared.global [%0], [%1], 16, %2;" :: "r"(d), "l"(s), "r"(sz));
}
__device__ __forceinline__ void ldm4(uint32_t* r, uint32_t a) {
    asm volatile("ldmatrix.sync.aligned.m8n8.x4.shared.b16 {%0,%1,%2,%3}, [%4];"
        : "=r"(r[0]), "=r"(r[1]), "=r"(r[2]), "=r"(r[3]) : "r"(a));
}
__device__ __forceinline__ void mma16816(float* c, const uint32_t* a, uint32_t b0, uint32_t b1) {
    asm volatile(
        "mma.sync.aligned.m16n8k16.row.col.f32.bf16.bf16.f32 "
        "{%0,%1,%2,%3}, {%4,%5,%6,%7}, {%8,%9}, {%0,%1,%2,%3};"
        : "+f"(c[0]), "+f"(c[1]), "+f"(c[2]), "+f"(c[3])
        : "r"(a[0]), "r"(a[1]), "r"(a[2]), "r"(a[3]), "r"(b0), "r"(b1));
}
__device__ __forceinline__ void split1(float x, bf16& h, bf16& l) {
    h = __float2bfloat16_rn(x);
    l = __float2bfloat16_rn(x - __bfloat162float(h));
}

// 3-stage swizzled SMEM: tiles of 128 rows x 64 B, unit = 16B, unit ^= (row>>1)&3
#define T3 8192
#define SM_TOTAL3 (12*T3)   // 98304 B per CTA
__device__ __forceinline__ uint32_t swst(int row, int kc) {
    return (uint32_t)(row*64 + ((kc ^ ((row>>1)&3)) << 4));
}

// ---------------- GEMM core (shared by all instantiations) ---------------------
template<int KWIN, bool RELU, bool MASK>
__device__ __forceinline__ void gemm_core(
    const bf16* __restrict__ Ahi, const bf16* __restrict__ Alo,
    const bf16* __restrict__ Whi, const bf16* __restrict__ Wlo,
    const float* __restrict__ bias, float* __restrict__ Y, int Cout,
    int row0, int n0, int tmask, const int* __restrict__ mellen, uint32_t sb)
{
    constexpr int NS = KWIN * 8;
    constexpr int K  = KWIN * 256;
    const int tid = threadIdx.x;
    const int wid = tid >> 5, lid = tid & 31;
    const int wm = wid >> 1, wn = wid & 1;
    const int tloc0 = row0 & tmask;
    const int gseg  = row0 - tloc0;
    const int Tb    = tmask + 1;

    // LDSM lane offsets (swizzled)
    const int rowA = wm*32 + (lid & 15);
    const int hA   = (lid >> 4) & 1;
    const int swA  = (rowA >> 1) & 3;
    const uint32_t offA0 = (uint32_t)(rowA*64 + ((hA ^ swA) << 4));
    const uint32_t offA1 = (uint32_t)(rowA*64 + (((2|hA) ^ swA) << 4));
    const int rowB = wn*64 + (lid & 7) + ((lid & 16) >> 1);
    const int hB   = (lid >> 3) & 1;
    const int swB  = (rowB >> 1) & 3;
    const uint32_t offB0 = (uint32_t)(rowB*64 + ((hB ^ swB) << 4));
    const uint32_t offB1 = (uint32_t)(rowB*64 + (((2|hB) ^ swB) << 4));

    float acc[2][8][4];
    #pragma unroll
    for (int i = 0; i < 2; i++)
        #pragma unroll
        for (int j = 0; j < 8; j++)
            #pragma unroll
            for (int e = 0; e < 4; e++) acc[i][j][e] = 0.f;

    auto load_stage = [&](int s, int st) {
        const int tap = (KWIN == 3) ? (s >> 3) : 0;
        const int cb  = (s & 7) * 32;
        #pragma unroll
        for (int h2 = 0; h2 < 2; h2++) {
            const int c = tid + h2*256;
            const int row = c >> 2, kc = c & 3;
            const int src = tloc0 + row + tap - (KWIN >> 1);
            const bool valid = (KWIN == 1) || (src >= 0 && src < Tb);
            const size_t go = (size_t)(gseg + (valid ? src : 0))*256 + cb + kc*8;
            const uint32_t d = swst(row, kc);
            cpa16(sb + st*T3       + d, Ahi + go, valid ? 16 : 0);
            cpa16(sb + (3+st)*T3   + d, Alo + go, valid ? 16 : 0);
        }
        #pragma unroll
        for (int h2 = 0; h2 < 2; h2++) {
            const int c = tid + h2*256;
            const int row = c >> 2, kc = c & 3;
            const size_t go = (size_t)(n0 + row)*K + s*32 + kc*8;
            const uint32_t d = swst(row, kc);
            cpa16(sb + (6+st)*T3 + d, Whi + go, 16);
            cpa16(sb + (9+st)*T3 + d, Wlo + go, 16);
        }
        asm volatile("cp.async.commit_group;");
    };

    auto compute_stage = [&](int st) {
        const uint32_t aHi = sb + st*T3,     aLo = sb + (3+st)*T3;
        const uint32_t bHi = sb + (6+st)*T3, bLo = sb + (9+st)*T3;
        #pragma unroll
        for (int q = 0; q < 2; q++) {
            const uint32_t oA = q ? offA1 : offA0;
            const uint32_t oB = q ? offB1 : offB0;
            uint32_t ah[2][4], bh[4][4];
            ldm4(ah[0], aHi + oA);
            ldm4(ah[1], aHi + oA + 1024);
            #pragma unroll
            for (int p = 0; p < 4; p++) ldm4(bh[p], bHi + oB + p*1024);
            #pragma unroll
            for (int mt = 0; mt < 2; mt++)
                #pragma unroll
                for (int p = 0; p < 4; p++) {
                    mma16816(acc[mt][2*p],   ah[mt], bh[p][0], bh[p][1]);
                    mma16816(acc[mt][2*p+1], ah[mt], bh[p][2], bh[p][3]);
                }
            uint32_t al[2][4];
            ldm4(al[0], aLo + oA);
            ldm4(al[1], aLo + oA + 1024);
            #pragma unroll
            for (int mt = 0; mt < 2; mt++)
                #pragma unroll
                for (int p = 0; p < 4; p++) {
                    mma16816(acc[mt][2*p],   al[mt], bh[p][0], bh[p][1]);
                    mma16816(acc[mt][2*p+1], al[mt], bh[p][2], bh[p][3]);
                }
            uint32_t bl[4][4];
            #pragma unroll
            for (int p = 0; p < 4; p++) ldm4(bl[p], bLo + oB + p*1024);
            #pragma unroll
            for (int mt = 0; mt < 2; mt++)
                #pragma unroll
                for (int p = 0; p < 4; p++) {
                    mma16816(acc[mt][2*p],   ah[mt], bl[p][0], bl[p][1]);
                    mma16816(acc[mt][2*p+1], ah[mt], bl[p][2], bl[p][3]);
                }
        }
    };

    load_stage(0, 0);
    load_stage(1, 1);
    int stc = 0, stl = 2;
    #pragma unroll 1
    for (int s = 0; s < NS; s++) {
        if (s + 1 < NS) { asm volatile("cp.async.wait_group 1;"); }
        else            { asm volatile("cp.async.wait_group 0;"); }
        __syncthreads();
        compute_stage(stc);
        if (s + 2 < NS) load_stage(s + 2, stl);
        stc = (stc == 2) ? 0 : stc + 1;
        stl = (stl == 2) ? 0 : stl + 1;
    }

    const int mrow = row0 + wm*32;
    const int ncol = n0 + wn*64;
    const int ml = MASK ? mellen[(uint32_t)row0 / (uint32_t)Tb] : 0;
    #pragma unroll
    for (int mt = 0; mt < 2; mt++) {
        const int r = mrow + mt*16 + (lid >> 2);
        const bool m0 = MASK && ((r     & tmask) >= ml);
        const bool m1 = MASK && (((r+8) & tmask) >= ml);
        #pragma unroll
        for (int nt = 0; nt < 8; nt++) {
            const int c = ncol + nt*8 + (lid & 3)*2;
            const float bb0 = bias[c], bb1 = bias[c+1];
            float v0 = acc[mt][nt][0] + bb0, v1 = acc[mt][nt][1] + bb1;
            float v2 = acc[mt][nt][2] + bb0, v3 = acc[mt][nt][3] + bb1;
            if (RELU) { v0 = fmaxf(v0,0.f); v1 = fmaxf(v1,0.f); v2 = fmaxf(v2,0.f); v3 = fmaxf(v3,0.f); }
            if (m0) { v0 = 0.f; v1 = 0.f; }
            if (m1) { v2 = 0.f; v3 = 0.f; }
            *(float2*)(Y + (size_t)r*Cout + c)     = make_float2(v0, v1);
            *(float2*)(Y + (size_t)(r+8)*Cout + c) = make_float2(v2, v3);
        }
    }
}

// ---------------- GEMM kernels ---------------------------------------------------
// Dual: blockIdx.x < PB -> config 0 (pitch), else config 1 (duration)
__global__ __launch_bounds__(256, 2)
void gemm_dual(const bf16* Ah0, const bf16* Al0, const bf16* Wh0, const bf16* Wl0,
               const float* b0, float* Y0, int tm0,
               const bf16* Ah1, const bf16* Al1, const bf16* Wh1, const bf16* Wl1,
               const float* b1, float* Y1, int tm1, int PB) {
    extern __shared__ char smc[];
    const uint32_t sb = (uint32_t)__cvta_generic_to_shared(smc);
    const int bx = blockIdx.x;
    const int n0 = blockIdx.y * 128;
    if (bx < PB) {
        gemm_core<3,true,false>(Ah0, Al0, Wh0, Wl0, b0, Y0, 256, bx*128, n0, tm0, nullptr, sb);
    } else {
        gemm_core<3,true,false>(Ah1, Al1, Wh1, Wl1, b1, Y1, 256, (bx-PB)*128, n0, tm1, nullptr, sb);
    }
}

__global__ __launch_bounds__(256, 2)
void gemm_proj(const bf16* Ah, const bf16* Al, const bf16* Wh, const bf16* Wl,
               const float* b, float* Y, const int* mellen) {
    extern __shared__ char smc[];
    const uint32_t sb = (uint32_t)__cvta_generic_to_shared(smc);
    gemm_core<1,false,true>(Ah, Al, Wh, Wl, b, Y, 512,
                            blockIdx.x*128, blockIdx.y*128, 2047, mellen, sb);
}

// ---------------- merged weight prep ---------------------------------------------
__global__ void prep_all(const float* __restrict__ dp_w1, const float* __restrict__ dp_w2,
                         const float* __restrict__ pp_w1, const float* __restrict__ pp_w2,
                         const float* __restrict__ proj_w,
                         bf16* __restrict__ H, bf16* __restrict__ L) {
    int bid = blockIdx.x;
    if (bid < 3072) {
        int slot = bid / 768;
        const float* W = (slot == 0) ? dp_w1 : (slot == 1) ? dp_w2 : (slot == 2) ? pp_w1 : pp_w2;
        int o = (bid - slot*768) * 256 + threadIdx.x;
        int f = o / 768;
        int r = o - f * 768;
        int tap = r >> 8;
        int c = r & 255;
        float w = W[f*768 + c*3 + tap];
        bf16 h, l; split1(w, h, l);
        H[slot*WCONV + o] = h; L[slot*WCONV + o] = l;
    } else {
        int o = (bid - 3072) * 256 + threadIdx.x;
        int n = o >> 8;
        int k = o & 255;
        float w = proj_w[k*512 + n];
        bf16 h, l; split1(w, h, l);
        H[4*WCONV + o] = h; L[4*WCONV + o] = l;
    }
}

// ---------------- length regulator ------------------------------------------------
__global__ void length_reg(const int* __restrict__ dur, int* __restrict__ idxb,
                           int* __restrict__ mellen, float* __restrict__ out_mel) {
    __shared__ int cum[TSLEN];
    int b = blockIdx.x;
    int t = threadIdx.x;
    cum[t] = dur[b*TSLEN + t];
    __syncthreads();
    for (int off = 1; off < TSLEN; off <<= 1) {
        int v = (t >= off) ? cum[t - off] : 0;
        __syncthreads();
        cum[t] += v;
        __syncthreads();
    }
    int ml = min(cum[TSLEN-1], MAXMEL);
    if (t == 0) { mellen[b] = ml; out_mel[b] = (float)ml; }
    for (int m = t; m < MAXMEL; m += TSLEN) {
        int lo = 0, hi = TSLEN;
        while (lo < hi) { int mid = (lo + hi) >> 1; if (cum[mid] <= m) lo = mid + 1; else hi = mid; }
        idxb[b*MAXMEL + m] = min(lo, TSLEN - 1);
    }
}

// ---------------- gather (pitch) + split (duration) in one launch -----------------
__global__ void gather_split(const float* __restrict__ ling, const int* __restrict__ idxb,
                             const int* __restrict__ mellen,
                             bf16* __restrict__ dh, bf16* __restrict__ dl) {
    int bx = blockIdx.x;
    if (bx < 16384) {                 // gather: 4 rows per block
        int row = bx*4 + (threadIdx.x >> 6);
        int t = threadIdx.x & 63;
        int b = row >> 11;
        int m = row & (MAXMEL - 1);
        bool masked = (m >= mellen[b]);
        int src = idxb[row];
        const float4* s = (const float4*)(ling + ((size_t)b*TSLEN + src)*DD);
        float4 v = masked ? make_float4(0.f,0.f,0.f,0.f) : s[t];
        ((float4*)(g_bufX + (size_t)row*DD))[t] = v;
        bf16 h0,h1,h2,h3, l0,l1,l2,l3;
        split1(v.x,h0,l0); split1(v.y,h1,l1); split1(v.z,h2,l2); split1(v.w,h3,l3);
        ((ushort4*)(g_xh + (size_t)row*DD))[t] =
            make_ushort4(__bfloat16_as_ushort(h0), __bfloat16_as_ushort(h1),
                         __bfloat16_as_ushort(h2), __bfloat16_as_ushort(h3));
        ((ushort4*)(g_xl + (size_t)row*DD))[t] =
            make_ushort4(__bfloat16_as_ushort(l0), __bfloat16_as_ushort(l1),
                         __bfloat16_as_ushort(l2), __bfloat16_as_ushort(l3));
    } else {                          // split duration input
        int i = (bx - 16384)*256 + threadIdx.x;      // float4 index, < 524288
        float4 v = ((const float4*)ling)[i];
        bf16 h0,h1,h2,h3, l0,l1,l2,l3;
        split1(v.x,h0,l0); split1(v.y,h1,l1); split1(v.z,h2,l2); split1(v.w,h3,l3);
        ((ushort4*)dh)[i] = make_ushort4(__bfloat16_as_ushort(h0), __bfloat16_as_ushort(h1),
                                         __bfloat16_as_ushort(h2), __bfloat16_as_ushort(h3));
        ((ushort4*)dl)[i] = make_ushort4(__bfloat16_as_ushort(l0), __bfloat16_as_ushort(l1),
                                         __bfloat16_as_ushort(l2), __bfloat16_as_ushort(l3));
    }
}

// ---------------- LayerNorm + bf16 split (dual workload) --------------------------
__global__ void ln_dual(const float* __restrict__ H0, const float* __restrict__ g0,
                        const float* __restrict__ be0, bf16* __restrict__ hi0, bf16* __restrict__ lo0,
                        int R0,
                        const float* __restrict__ H1, const float* __restrict__ g1,
                        const float* __restrict__ be1, bf16* __restrict__ hi1, bf16* __restrict__ lo1) {
    int bx = blockIdx.x;
    const float *H, *g, *be;
    bf16 *hi, *lo;
    int row;
    if (bx < R0) { H = H0; g = g0; be = be0; hi = hi0; lo = lo0; row = bx; }
    else         { H = H1; g = g1; be = be1; hi = hi1; lo = lo1; row = bx - R0; }
    int t = threadIdx.x;
    float x = H[(size_t)row*FF + t];
    float v1 = x, v2 = x*x;
    #pragma unroll
    for (int o = 16; o; o >>= 1) {
        v1 += __shfl_down_sync(0xffffffffu, v1, o);
        v2 += __shfl_down_sync(0xffffffffu, v2, o);
    }
    __shared__ float s1[8], s2[8];
    __shared__ float mean, rstd;
    int w = t >> 5, l = t & 31;
    if (l == 0) { s1[w] = v1; s2[w] = v2; }
    __syncthreads();
    if (t == 0) {
        float a = 0.f, q = 0.f;
        #pragma unroll
        for (int i = 0; i < 8; i++) { a += s1[i]; q += s2[i]; }
        float m = a * (1.f/256.f);
        float var = q * (1.f/256.f) - m*m;
        mean = m;
        rstd = rsqrtf(var + 1e-5f);
    }
    __syncthreads();
    float y = (x - mean) * rstd * g[t] + be[t];
    bf16 h, ll; split1(y, h, ll);
    hi[(size_t)row*FF + t] = h;
    lo[(size_t)row*FF + t] = ll;
}

// ---------------- heads (pitch + duration) in one launch --------------------------
__global__ void heads_dual(const float* __restrict__ Hp, const float* __restrict__ gp,
                           const float* __restrict__ bep, const float* __restrict__ lwp,
                           const float* __restrict__ lbp, const float* __restrict__ bins,
                           const float* __restrict__ emb, const int* __restrict__ mellen,
                           float* __restrict__ pout,
                           const float* __restrict__ Hd, const float* __restrict__ gd,
                           const float* __restrict__ bed, const float* __restrict__ lwd,
                           const float* __restrict__ lbd, float* __restrict__ dout) {
    int bx = blockIdx.x;
    int t = threadIdx.x;
    int w = t >> 5, l = t & 31;
    __shared__ float s1[8], s2[8];
    __shared__ float mean, rstd;
    __shared__ int bkt;

    const bool isPitch = (bx < BB*MAXMEL);
    const int row = isPitch ? bx : bx - BB*MAXMEL;
    const float* H  = isPitch ? Hp  : Hd;
    const float* g  = isPitch ? gp  : gd;
    const float* be = isPitch ? bep : bed;
    const float* lw = isPitch ? lwp : lwd;
    const float* lb = isPitch ? lbp : lbd;

    float x = H[(size_t)row*FF + t];
    float v1 = x, v2 = x*x;
    #pragma unroll
    for (int o = 16; o; o >>= 1) {
        v1 += __shfl_down_sync(0xffffffffu, v1, o);
        v2 += __shfl_down_sync(0xffffffffu, v2, o);
    }
    if (l == 0) { s1[w] = v1; s2[w] = v2; }
    __syncthreads();
    if (t == 0) {
        float a = 0.f, q = 0.f;
        #pragma unroll
        for (int i = 0; i < 8; i++) { a += s1[i]; q += s2[i]; }
        float mm = a * (1.f/256.f);
        float var = q * (1.f/256.f) - mm*mm;
        mean = mm;
        rstd = rsqrtf(var + 1e-5f);
    }
    __syncthreads();
    float y = (x - mean) * rstd * g[t] + be[t];
    float v = y * lw[t];
    #pragma unroll
    for (int o = 16; o; o >>= 1) v += __shfl_down_sync(0xffffffffu, v, o);
    if (l == 0) s1[w] = v;
    __syncthreads();

    if (isPitch) {
        int b = row >> 11;
        int m = row & (MAXMEL - 1);
        if (t == 0) {
            float a = 0.f;
            #pragma unroll
            for (int i = 0; i < 8; i++) a += s1[i];
            a += lb[0];
            if (m >= mellen[b]) a = 0.f;       // mask BEFORE bucketize
            pout[row] = a;
            int lo = 0, hi = NBINS - 1;
            while (lo < hi) { int mid = (lo + hi) >> 1; if (bins[mid] < a) lo = mid + 1; else hi = mid; }
            bkt = lo;
        }
        __syncthreads();
        float xv = g_bufX[(size_t)row*DD + t] + emb[(size_t)bkt*DD + t];
        bf16 h, ll; split1(xv, h, ll);
        g_xh[(size_t)row*DD + t] = h;
        g_xl[(size_t)row*DD + t] = ll;
    } else {
        if (t == 0) {
            float a = 0.f;
            #pragma unroll
            for (int i = 0; i < 8; i++) a += s1[i];
            dout[row] = a + lb[0];
        }
    }
}

// ------------------------------- launch ------------------------------------------
extern "C" void kernel_launch(void* const* d_in, const int* in_sizes, int n_in,
                              void* d_out, int out_size) {
    const float* ling   = (const float*)d_in[0];
    const int*   dur    = (const int*)  d_in[1];
    const float* dp_w1  = (const float*)d_in[3];
    const float* dp_b1  = (const float*)d_in[4];
    const float* dp_g1  = (const float*)d_in[5];
    const float* dp_be1 = (const float*)d_in[6];
    const float* dp_w2  = (const float*)d_in[7];
    const float* dp_b2  = (const float*)d_in[8];
    const float* dp_g2  = (const float*)d_in[9];
    const float* dp_be2 = (const float*)d_in[10];
    const float* dp_lw  = (const float*)d_in[11];
    const float* dp_lb  = (const float*)d_in[12];
    const float* pp_w1  = (const float*)d_in[13];
    const float* pp_b1  = (const float*)d_in[14];
    const float* pp_g1  = (const float*)d_in[15];
    const float* pp_be1 = (const float*)d_in[16];
    const float* pp_w2  = (const float*)d_in[17];
    const float* pp_b2  = (const float*)d_in[18];
    const float* pp_g2  = (const float*)d_in[19];
    const float* pp_be2 = (const float*)d_in[20];
    const float* pp_lw  = (const float*)d_in[21];
    const float* pp_lb  = (const float*)d_in[22];
    const float* bins   = (const float*)d_in[23];
    const float* emb    = (const float*)d_in[24];
    const float* proj_w = (const float*)d_in[25];
    const float* proj_b = (const float*)d_in[26];

    float* out = (float*)d_out;

    float *bufA, *bufB;
    bf16 *wh, *wl, *xh, *xl, *yh, *yl, *dh, *dl;
    int *idxb, *mellen;
    cudaGetSymbolAddress((void**)&bufA,   g_bufA);
    cudaGetSymbolAddress((void**)&bufB,   g_bufB);
    cudaGetSymbolAddress((void**)&wh,     g_wh);
    cudaGetSymbolAddress((void**)&wl,     g_wl);
    cudaGetSymbolAddress((void**)&xh,     g_xh);
    cudaGetSymbolAddress((void**)&xl,     g_xl);
    cudaGetSymbolAddress((void**)&yh,     g_yh);
    cudaGetSymbolAddress((void**)&yl,     g_yl);
    cudaGetSymbolAddress((void**)&dh,     g_dh);
    cudaGetSymbolAddress((void**)&dl,     g_dl);
    cudaGetSymbolAddress((void**)&idxb,   g_idx);
    cudaGetSymbolAddress((void**)&mellen, g_mellen);

    cudaFuncSetAttribute(gemm_dual, cudaFuncAttributeMaxDynamicSharedMemorySize, SM_TOTAL3);
    cudaFuncSetAttribute(gemm_proj, cudaFuncAttributeMaxDynamicSharedMemorySize, SM_TOTAL3);

    // 1: length regulator
    length_reg<<<BB, TSLEN>>>(dur, idxb, mellen, out + MEL_OFF);
    // 2: weight prep
    prep_all<<<3584, 256>>>(dp_w1, dp_w2, pp_w1, pp_w2, proj_w, wh, wl);
    // 3: gather (pitch) + split (duration)
    gather_split<<<16384 + 2048, 256>>>(ling, idxb, mellen, dh, dl);
    // 4: conv1 dual (pitch 512 blocks + dur 64 blocks) <- ncu capture slot
    gemm_dual<<<dim3(512 + 64, 2), 256, SM_TOTAL3>>>(
        xh, xl, wh + 2*WCONV, wl + 2*WCONV, pp_b1, bufA, 2047,
        dh, dl, wh + 0*WCONV, wl + 0*WCONV, dp_b1, bufB, 255, 512);
    // 5: LN dual (pitch -> yh/yl, dur -> dh/dl)
    ln_dual<<<BB*MAXMEL + BB*TSLEN, 256>>>(bufA, pp_g1, pp_be1, yh, yl, BB*MAXMEL,
                                           bufB, dp_g1, dp_be1, dh, dl);
    // 6: conv2 dual
    gemm_dual<<<dim3(512 + 64, 2), 256, SM_TOTAL3>>>(
        yh, yl, wh + 3*WCONV, wl + 3*WCONV, pp_b2, bufA, 2047,
        dh, dl, wh + 1*WCONV, wl + 1*WCONV, dp_b2, bufB, 255, 512);
    // 7: heads dual (pitch: LN+dot+bucketize+emb+split; dur: LN+dot)
    heads_dual<<<BB*MAXMEL + BB*TSLEN, 256>>>(
        bufA, pp_g2, pp_be2, pp_lw, pp_lb, bins, emb, mellen, out + PITCH_OFF,
        bufB, dp_g2, dp_be2, dp_lw, dp_lb, out + LOGDUR_OFF);
    // 8: final projection (masked) into d_out
    gemm_proj<<<dim3(512, 4), 256, SM_TOTAL3>>>(
        xh, xl, wh + 4*WCONV, wl + 4*WCONV, proj_b, out, mellen);
}